// round 10
// baseline (speedup 1.0000x reference)
#include <cuda_runtime.h>
#include <cstdint>

// ---------------------------------------------------------------------------
// Router: r[b,e] = || W[e] @ x[b] ||_2
//   x: [8192,4096] f32, W: [16,64,4096] f32, out: [8192,16] f32
// GEMM C = X @ W^T via mma.sync.m16n8k16.bf16 (base sm_103 target; tcgen05
// rejected by this build's ptxas).
// R10 vs R9 (250us, GEMM ~218us): GEMM is HMMA-instruction-path bound
// (~3.2 cyc/HMMA/SM, proven by R7->R9 proportionality). Remaining waste was
// wave quantization: 256 tiles over 148 SMs = 2.0 waves vs ideal 1.73
// (~29us). -> BM=64/BN=128: 1024 tiles, 6.92 waves, quantization 1.2%;
// occ 2 (smem 110.6KB/CTA) so CTA prologue/epilogue overlap. Prep kernels
// fused into one launch. Expert (64 cols) now spans 2 warps -> cross-warp
// sum-of-squares reduction via 1KB static smem in the epilogue.
// ---------------------------------------------------------------------------

#define BDIM   8192
#define DDIM   4096
#define EDIM   16
#define NTOT   1024
#define BM     64
#define BN     128
#define BK     64                      /* bf16 cols per stage = 128B/row    */
#define STAGES 3
#define KT     (DDIM / BK)             /* 64 mainloop iterations            */
#define RSB    192                     /* smem row stride bytes (=64 mod 128:
                                          conflict-free 16B phases)          */
#define A_BYTES (BM * RSB)             /* 12288 */
#define B_BYTES (BN * RSB)             /* 24576 */
#define STG_BYTES (A_BYTES + B_BYTES)  /* 36864 */
#define SMEM_BYTES (STAGES * STG_BYTES)/* 110592 -> 2 CTAs/SM               */

#define NXU4 ((size_t)BDIM * DDIM / 8) /* uint4 count for x                 */
#define NWU4 ((size_t)NTOT * DDIM / 8)

// bf16 scratch copies of the inputs (module-scope __device__ = legal scratch)
__device__ uint4 g_xb[NXU4];   // 67 MB
__device__ uint4 g_wb[NWU4];   //  8.4 MB

__device__ __forceinline__ void mma_bf16(float c[4],
                                         uint32_t a0, uint32_t a1,
                                         uint32_t a2, uint32_t a3,
                                         uint32_t b0, uint32_t b1) {
    asm volatile(
        "mma.sync.aligned.m16n8k16.row.col.f32.bf16.bf16.f32 "
        "{%0,%1,%2,%3}, {%4,%5,%6,%7}, {%8,%9}, {%0,%1,%2,%3};"
        : "+f"(c[0]), "+f"(c[1]), "+f"(c[2]), "+f"(c[3])
        : "r"(a0), "r"(a1), "r"(a2), "r"(a3), "r"(b0), "r"(b1));
}

__device__ __forceinline__ void cp16(uint32_t dst, const void* src) {
    asm volatile("cp.async.cg.shared.global [%0], [%1], 16;"
                 :: "r"(dst), "l"(src) : "memory");
}

__device__ __forceinline__ uint32_t pack_bf16x2(float lo, float hi) {
    uint32_t r;
    asm("cvt.rn.bf16x2.f32 %0, %1, %2;" : "=r"(r) : "f"(hi), "f"(lo));
    return r;
}

// ---------------------------------------------------------------------------
// Fused prep: f32 -> bf16 (RN, unbiased) for both x and w in one launch.
// Each thread converts 8 floats -> 1 uint4.
// ---------------------------------------------------------------------------
__global__ void prep_xw(const float4* __restrict__ x,
                        const float4* __restrict__ w) {
    size_t i = (size_t)blockIdx.x * blockDim.x + threadIdx.x;
    const float4* src;
    uint4* dst;
    if (i < NXU4) {
        src = x + 2 * i;           dst = g_xb + i;
    } else {
        size_t j = i - NXU4;
        if (j >= NWU4) return;
        src = w + 2 * j;           dst = g_wb + j;
    }
    float4 v0 = src[0], v1 = src[1];
    uint4 o;
    o.x = pack_bf16x2(v0.x, v0.y);
    o.y = pack_bf16x2(v0.z, v0.w);
    o.z = pack_bf16x2(v1.x, v1.y);
    o.w = pack_bf16x2(v1.z, v1.w);
    *dst = o;
}

// ---------------------------------------------------------------------------
// grid = (NTOT/BN = 8, BDIM/BM = 128) = 1024 CTAs, n fastest (A L2 reuse).
// 8 warps: 2(m) x 4(n); warp tile 32x32. k-slot remap per 32-col chunk:
// one LDS.128 per row feeds both m16n8k16 instances (halves .x/.y vs .z/.w).
// ---------------------------------------------------------------------------
__global__ __launch_bounds__(256, 2)
void router_kernel(float* __restrict__ out) {
    extern __shared__ char smem[];
    __shared__ float red[64][4];             // cross-warp expert partials

    const int tid  = threadIdx.x;
    const int lane = tid & 31;
    const int wid  = tid >> 5;
    const int wm   = wid & 1;                // 0..1 (32 m-rows each)
    const int wn   = wid >> 1;               // 0..3 (32 n-cols each)

    const int m_base = blockIdx.y * BM;
    const int n_base = blockIdx.x * BN;

    // ---- cp.async producer: thread -> (row = tid/8, 16B chunk = tid%8) ----
    const int lrow = tid >> 3;               // 0..31
    const int lch  = tid & 7;                // 0..7
    const char* gA = (const char*)g_xb
                   + ((size_t)(m_base + lrow) * DDIM + lch * 8) * 2;
    const char* gB = (const char*)g_wb
                   + ((size_t)(n_base + lrow) * DDIM + lch * 8) * 2;
    const uint32_t sbase = (uint32_t)__cvta_generic_to_shared(smem);
    const uint32_t sA0 = sbase + (uint32_t)(lrow * RSB + lch * 16);
    const uint32_t sB0 = sA0 + A_BYTES;

    auto load_stage = [&](int s, int kb /*bf16 col offset*/) {
        const uint32_t so = (uint32_t)(s * STG_BYTES);
        const char* ga = gA + (size_t)kb * 2;
#pragma unroll
        for (int p = 0; p < BM / 32; ++p)    // 2 passes
            cp16(sA0 + so + (uint32_t)(p * 32 * RSB),
                 ga + (size_t)(p * 32) * DDIM * 2);
        const char* gb = gB + (size_t)kb * 2;
#pragma unroll
        for (int p = 0; p < BN / 32; ++p)    // 4 passes
            cp16(sB0 + so + (uint32_t)(p * 32 * RSB),
                 gb + (size_t)(p * 32) * DDIM * 2);
    };

#pragma unroll
    for (int s = 0; s < STAGES - 1; ++s) {
        load_stage(s, s * BK);
        asm volatile("cp.async.commit_group;" ::: "memory");
    }

    float acc[2][4][4];
#pragma unroll
    for (int mt = 0; mt < 2; ++mt)
#pragma unroll
        for (int nt = 0; nt < 4; ++nt)
#pragma unroll
            for (int i = 0; i < 4; ++i) acc[mt][nt][i] = 0.f;

    const int g = lane >> 2;                 // group (row) id
    const int q = lane & 3;                  // quad id
    const char* Aw = smem + (wm * 32 + g) * RSB + q * 16;
    const char* Bw = smem + A_BYTES + (wn * 32 + g) * RSB + q * 16;

#pragma unroll 1
    for (int kt = 0; kt < KT; ++kt) {
        asm volatile("cp.async.wait_group %0;" :: "n"(STAGES - 2) : "memory");
        __syncthreads();

        const int pf = kt + STAGES - 1;
        if (pf < KT) load_stage(pf % STAGES, pf * BK);
        asm volatile("cp.async.commit_group;" ::: "memory");

        const int cur = kt % STAGES;
        const char* Ac = Aw + cur * STG_BYTES;
        const char* Bc = Bw + cur * STG_BYTES;

#pragma unroll
        for (int c2 = 0; c2 < 2; ++c2) {     // two 32-col chunks per stage
            const int co = c2 * 64;
            uint4 al[2], ah[2];              // A rows g, g+8 per mt
#pragma unroll
            for (int mt = 0; mt < 2; ++mt) {
                const char* p = Ac + mt * 16 * RSB + co;
                al[mt] = *reinterpret_cast<const uint4*>(p);
                ah[mt] = *reinterpret_cast<const uint4*>(p + 8 * RSB);
            }
            uint4 bv[4];
#pragma unroll
            for (int nt = 0; nt < 4; ++nt)
                bv[nt] = *reinterpret_cast<const uint4*>(Bc + nt * 8 * RSB + co);

            // instance 0: fragment halves .x/.y — 8 independent acc chains
#pragma unroll
            for (int mt = 0; mt < 2; ++mt)
#pragma unroll
                for (int nt = 0; nt < 4; ++nt)
                    mma_bf16(acc[mt][nt],
                             al[mt].x, ah[mt].x, al[mt].y, ah[mt].y,
                             bv[nt].x, bv[nt].y);
            // instance 1: fragment halves .z/.w
#pragma unroll
            for (int mt = 0; mt < 2; ++mt)
#pragma unroll
                for (int nt = 0; nt < 4; ++nt)
                    mma_bf16(acc[mt][nt],
                             al[mt].z, ah[mt].z, al[mt].w, ah[mt].w,
                             bv[nt].z, bv[nt].w);
        }
    }

    // ---- epilogue ----------------------------------------------------------
    // Each warp: sum of squares over its 32 n-cols -> partial per row.
    // red[row][wn] ; experts: e_local 0 <- wn{0,1}, e_local 1 <- wn{2,3}.
#pragma unroll
    for (int mt = 0; mt < 2; ++mt) {
        float s0 = 0.f, s1 = 0.f;
#pragma unroll
        for (int nt = 0; nt < 4; ++nt) {
            s0 = fmaf(acc[mt][nt][0], acc[mt][nt][0], s0);
            s0 = fmaf(acc[mt][nt][1], acc[mt][nt][1], s0);
            s1 = fmaf(acc[mt][nt][2], acc[mt][nt][2], s1);
            s1 = fmaf(acc[mt][nt][3], acc[mt][nt][3], s1);
        }
        s0 += __shfl_xor_sync(0xffffffffu, s0, 1);
        s0 += __shfl_xor_sync(0xffffffffu, s0, 2);
        s1 += __shfl_xor_sync(0xffffffffu, s1, 1);
        s1 += __shfl_xor_sync(0xffffffffu, s1, 2);
        if ((lane & 3) == 0) {
            const int row = wm * 32 + mt * 16 + g;
            red[row][wn]     = s0;
            red[row + 8][wn] = s1;
        }
    }
    __syncthreads();

    if (tid < 128) {
        const int row = tid & 63;
        const int el  = tid >> 6;            // expert-local 0/1
        const float s = red[row][2 * el] + red[row][2 * el + 1];
        out[(size_t)(m_base + row) * EDIM + blockIdx.x * 2 + el] = sqrtf(s);
    }
}

// ---------------------------------------------------------------------------
extern "C" void kernel_launch(void* const* d_in, const int* in_sizes, int n_in,
                              void* d_out, int out_size) {
    (void)in_sizes; (void)n_in; (void)out_size;
    const float* x = (const float*)d_in[0];   // [8192, 4096]
    const float* w = (const float*)d_in[1];   // [16, 64, 4096]
    float* out = (float*)d_out;               // [8192, 16]

    const size_t total = NXU4 + NWU4;
    prep_xw<<<(unsigned)((total + 255) / 256), 256>>>(
        (const float4*)x, (const float4*)w);

    cudaFuncSetAttribute(router_kernel,
                         cudaFuncAttributeMaxDynamicSharedMemorySize, SMEM_BYTES);
    router_kernel<<<dim3(NTOT / BN, BDIM / BM), 256, SMEM_BYTES>>>(out);
}

// round 11
// speedup vs baseline: 1.0572x; 1.0572x over previous
#include <cuda_runtime.h>
#include <cstdint>

// ---------------------------------------------------------------------------
// Router: r[b,e] = || W[e] @ x[b] ||_2
//   x: [8192,4096] f32, W: [16,64,4096] f32, out: [8192,16] f32
// GEMM C = X @ W^T via mma.sync.m16n8k16.bf16 (base sm_103 target).
// R11 vs R9 (250us = 27.6 prep_x + ~4 prep_w + 218 GEMM) and R10 (279us,
// small-tile regression): GEMM is pinned by the HMMA instruction path
// (~13.7 cyc/HMMA/SMSP; invariant to warps & instruction mix), so all
// non-HMMA work rides free. -> delete prep_x: A tile staged as RAW f32 via
// cp.async, converted to bf16 fragments in-register after LDS (packs are
// free under the HMMA pin). Tiles back to BM=128/BN=256 (best compute/byte).
// 2 stages (A-f32 stage is 43KB; 2x(43+48)KB = 184KB SMEM).
// ---------------------------------------------------------------------------

#define BDIM   8192
#define DDIM   4096
#define EDIM   16
#define NTOT   1024
#define BM     128
#define BN     256
#define BK     64                      /* k-cols per stage                   */
#define STAGES 2
#define KT     (DDIM / BK)             /* 64 mainloop iterations             */
#define RSA    336                     /* A row stride bytes (f32 rows, 256B
                                          data): (21g+2q+h)%8 conflict-free  */
#define RSB    192                     /* B row stride bytes (bf16, 128B data)*/
#define A_BYTES (BM * RSA)             /* 43008 */
#define B_BYTES (BN * RSB)             /* 49152 */
#define STG_BYTES (A_BYTES + B_BYTES)  /* 92160 */
#define SMEM_BYTES (STAGES * STG_BYTES)/* 184320 */

#define NWU4 ((size_t)NTOT * DDIM / 8)

// bf16 scratch for W only (module-scope __device__ = legal scratch)
__device__ uint4 g_wb[NWU4];           // 8.4 MB

__device__ __forceinline__ void mma_bf16(float c[4],
                                         uint32_t a0, uint32_t a1,
                                         uint32_t a2, uint32_t a3,
                                         uint32_t b0, uint32_t b1) {
    asm volatile(
        "mma.sync.aligned.m16n8k16.row.col.f32.bf16.bf16.f32 "
        "{%0,%1,%2,%3}, {%4,%5,%6,%7}, {%8,%9}, {%0,%1,%2,%3};"
        : "+f"(c[0]), "+f"(c[1]), "+f"(c[2]), "+f"(c[3])
        : "r"(a0), "r"(a1), "r"(a2), "r"(a3), "r"(b0), "r"(b1));
}

__device__ __forceinline__ void cp16(uint32_t dst, const void* src) {
    asm volatile("cp.async.cg.shared.global [%0], [%1], 16;"
                 :: "r"(dst), "l"(src) : "memory");
}

__device__ __forceinline__ uint32_t pack_bf16x2(float lo, float hi) {
    uint32_t r;
    asm("cvt.rn.bf16x2.f32 %0, %1, %2;" : "=r"(r) : "f"(hi), "f"(lo));
    return r;
}

// ---------------------------------------------------------------------------
// Prep (W only): f32 -> bf16 RN. 8.4 MB out, ~4us.
// ---------------------------------------------------------------------------
__global__ void prep_w(const float4* __restrict__ w) {
    size_t i = (size_t)blockIdx.x * blockDim.x + threadIdx.x;
    if (i >= NWU4) return;
    float4 v0 = w[2 * i], v1 = w[2 * i + 1];
    uint4 o;
    o.x = pack_bf16x2(v0.x, v0.y);
    o.y = pack_bf16x2(v0.z, v0.w);
    o.z = pack_bf16x2(v1.x, v1.y);
    o.w = pack_bf16x2(v1.z, v1.w);
    g_wb[i] = o;
}

// ---------------------------------------------------------------------------
// grid = (NTOT/BN = 4, BDIM/BM = 64), n fastest (A reused via L2).
// 8 warps: 2(m) x 4(n); warp tile 64x64 = one expert per warp.
// k-slot remap per 32-col chunk: thread quad q owns k-cols [8q..8q+7]
// identically for A and B, so fragments for two m16n8k16 instances come from
// one 32B A read (2x LDS.128 f32 -> 8 packs) and one LDS.128 B read.
// ---------------------------------------------------------------------------
__global__ __launch_bounds__(256, 1)
void router_kernel(const float* __restrict__ x, float* __restrict__ out) {
    extern __shared__ char smem[];

    const int tid  = threadIdx.x;
    const int lane = tid & 31;
    const int wid  = tid >> 5;
    const int wm   = wid & 1;
    const int wn   = wid >> 1;

    const int m_base = blockIdx.y * BM;
    const int n_base = blockIdx.x * BN;

    const uint32_t sbase = (uint32_t)__cvta_generic_to_shared(smem);

    // ---- A producer (f32): thread -> (row = tid/16, 16B chunk = tid%16) ----
    const int arow = tid >> 4;               // 0..15
    const int ach  = tid & 15;               // 0..15 (16B chunks of 256B row)
    const float* gA = x + (size_t)(m_base + arow) * DDIM + ach * 4;
    const uint32_t sA0 = sbase + (uint32_t)(arow * RSA + ach * 16);

    // ---- B producer (bf16): thread -> (row = tid/8, 16B chunk = tid%8) ----
    const int brow = tid >> 3;               // 0..31
    const int bch  = tid & 7;
    const char* gB = (const char*)g_wb
                   + ((size_t)(n_base + brow) * DDIM + bch * 8) * 2;
    const uint32_t sB0 = sbase + (uint32_t)A_BYTES
                       + (uint32_t)(brow * RSB + bch * 16);

    auto load_stage = [&](int s, int kb /*k col offset*/) {
        const uint32_t so = (uint32_t)(s * STG_BYTES);
        const float* ga = gA + kb;
#pragma unroll
        for (int p = 0; p < BM / 16; ++p)    // 8 passes of 16 rows (A, f32)
            cp16(sA0 + so + (uint32_t)(p * 16 * RSA),
                 ga + (size_t)(p * 16) * DDIM);
        const char* gb = gB + (size_t)kb * 2;
#pragma unroll
        for (int p = 0; p < BN / 32; ++p)    // 8 passes of 32 rows (B, bf16)
            cp16(sB0 + so + (uint32_t)(p * 32 * RSB),
                 gb + (size_t)(p * 32) * DDIM * 2);
    };

    load_stage(0, 0);
    asm volatile("cp.async.commit_group;" ::: "memory");

    float acc[4][8][4];
#pragma unroll
    for (int mt = 0; mt < 4; ++mt)
#pragma unroll
        for (int nt = 0; nt < 8; ++nt)
#pragma unroll
            for (int i = 0; i < 4; ++i) acc[mt][nt][i] = 0.f;

    const int g = lane >> 2;                 // group (row) id
    const int q = lane & 3;                  // quad id
    const char* Aw = smem + (wm * 64 + g) * RSA + q * 32;
    const char* Bw = smem + A_BYTES + (wn * 64 + g) * RSB + q * 16;

#pragma unroll 1
    for (int kt = 0; kt < KT; ++kt) {
        asm volatile("cp.async.wait_group 0;" ::: "memory");
        __syncthreads();

        const int pf = kt + STAGES - 1;
        if (pf < KT) load_stage(pf % STAGES, pf * BK);
        asm volatile("cp.async.commit_group;" ::: "memory");

        const int cur = kt % STAGES;
        const char* Ac = Aw + cur * STG_BYTES;
        const char* Bc = Bw + cur * STG_BYTES;

#pragma unroll
        for (int c2 = 0; c2 < 2; ++c2) {     // two 32-col chunks per stage
            // A: rows g, g+8 per mt; 32B f32 -> uint4 bf16 fragment
            uint4 al[4], ah[4];
#pragma unroll
            for (int mt = 0; mt < 4; ++mt) {
                const char* p = Ac + mt * 16 * RSA + c2 * 128;
                float4 l0 = *reinterpret_cast<const float4*>(p);
                float4 l1 = *reinterpret_cast<const float4*>(p + 16);
                al[mt].x = pack_bf16x2(l0.x, l0.y);
                al[mt].y = pack_bf16x2(l0.z, l0.w);
                al[mt].z = pack_bf16x2(l1.x, l1.y);
                al[mt].w = pack_bf16x2(l1.z, l1.w);
                float4 h0 = *reinterpret_cast<const float4*>(p + 8 * RSA);
                float4 h1 = *reinterpret_cast<const float4*>(p + 8 * RSA + 16);
                ah[mt].x = pack_bf16x2(h0.x, h0.y);
                ah[mt].y = pack_bf16x2(h0.z, h0.w);
                ah[mt].z = pack_bf16x2(h1.x, h1.y);
                ah[mt].w = pack_bf16x2(h1.z, h1.w);
            }
            uint4 bv[8];
#pragma unroll
            for (int nt = 0; nt < 8; ++nt)
                bv[nt] = *reinterpret_cast<const uint4*>(
                             Bc + nt * 8 * RSB + c2 * 64);

            // instance 0: fragment halves .x/.y — 32 independent acc chains
#pragma unroll
            for (int mt = 0; mt < 4; ++mt)
#pragma unroll
                for (int nt = 0; nt < 8; ++nt)
                    mma_bf16(acc[mt][nt],
                             al[mt].x, ah[mt].x, al[mt].y, ah[mt].y,
                             bv[nt].x, bv[nt].y);
            // instance 1: fragment halves .z/.w
#pragma unroll
            for (int mt = 0; mt < 4; ++mt)
#pragma unroll
                for (int nt = 0; nt < 8; ++nt)
                    mma_bf16(acc[mt][nt],
                             al[mt].z, ah[mt].z, al[mt].w, ah[mt].w,
                             bv[nt].z, bv[nt].w);
        }
    }

    // ---- epilogue: ||.||_2 over this warp's 64 n-cols (one expert) --------
    const int e = blockIdx.x * (BN / 64) + wn;
#pragma unroll
    for (int mt = 0; mt < 4; ++mt) {
        float s0 = 0.f, s1 = 0.f;
#pragma unroll
        for (int nt = 0; nt < 8; ++nt) {
            s0 = fmaf(acc[mt][nt][0], acc[mt][nt][0], s0);
            s0 = fmaf(acc[mt][nt][1], acc[mt][nt][1], s0);
            s1 = fmaf(acc[mt][nt][2], acc[mt][nt][2], s1);
            s1 = fmaf(acc[mt][nt][3], acc[mt][nt][3], s1);
        }
        s0 += __shfl_xor_sync(0xffffffffu, s0, 1);
        s0 += __shfl_xor_sync(0xffffffffu, s0, 2);
        s1 += __shfl_xor_sync(0xffffffffu, s1, 1);
        s1 += __shfl_xor_sync(0xffffffffu, s1, 2);
        if ((lane & 3) == 0) {
            const int row = m_base + wm * 64 + mt * 16 + g;
            out[(size_t)row * EDIM + e]       = sqrtf(s0);
            out[(size_t)(row + 8) * EDIM + e] = sqrtf(s1);
        }
    }
}

// ---------------------------------------------------------------------------
extern "C" void kernel_launch(void* const* d_in, const int* in_sizes, int n_in,
                              void* d_out, int out_size) {
    (void)in_sizes; (void)n_in; (void)out_size;
    const float* x = (const float*)d_in[0];   // [8192, 4096]
    const float* w = (const float*)d_in[1];   // [16, 64, 4096]
    float* out = (float*)d_out;               // [8192, 16]

    prep_w<<<(unsigned)((NWU4 + 255) / 256), 256>>>((const float4*)w);

    cudaFuncSetAttribute(router_kernel,
                         cudaFuncAttributeMaxDynamicSharedMemorySize, SMEM_BYTES);
    router_kernel<<<dim3(NTOT / BN, BDIM / BM), 256, SMEM_BYTES>>>(x, out);
}